// round 10
// baseline (speedup 1.0000x reference)
#include <cuda_runtime.h>
#include <cstdint>

#define NB 2
#define CIN 1024
#define HH 50
#define WW 50
#define SPAT 2500
#define SATN 51
#define SATSP (SATN * SATN)
#define RR 300
#define PQN 49
#define NCLS 21
#define ROWS_CLS 1029
#define ROWS_TOT 1225
#define COMB 25

// ---------------- scratch (static device memory; no allocations) ----------------
__device__ float4 g_ht4[(size_t)NB * SPAT * (CIN / 4)];   // tf32(h) channel-last
__device__ float4 g_sat4[(size_t)NB * SATSP * (CIN / 4)]; // SAT
__device__ float4 g_A4[(size_t)ROWS_TOT * (CIN / 4)];     // tf32(wc‖wl)
__device__ float4 g_B4[(size_t)CIN * (CIN / 4)];          // tf32(w1)
__device__ float4 g_W4[(size_t)ROWS_TOT * (CIN / 4)];     // folded weights (tf32 values)
__device__ float4 g_P4[(size_t)PQN * RR * (CIN / 4)];     // pooled vectors (tf32 values)
__device__ float  g_mask[PQN * RR];                       // cnt>0 mask
__device__ float  g_bias[ROWS_TOT];                       // folded bias
__device__ float  g_scr[(size_t)RR * COMB * PQN];         // per-(roi,c,pq) values

// fp32 -> tf32-rounded fp32
__device__ __forceinline__ float tf32r(float x) {
  unsigned u;
  asm("cvt.rna.tf32.f32 %0, %1;" : "=r"(u) : "f"(x));
  return __uint_as_float(u);
}
__device__ __forceinline__ float4 tf32r4(float4 v) {
  return make_float4(tf32r(v.x), tf32r(v.y), tf32r(v.z), tf32r(v.w));
}

// cp.async helpers
__device__ __forceinline__ void cpa16(void* smem, const void* gmem, int srcsz) {
  uint32_t s = (uint32_t)__cvta_generic_to_shared(smem);
  asm volatile("cp.async.cg.shared.global [%0], [%1], 16, %2;\n"
               :: "r"(s), "l"(gmem), "r"(srcsz));
}
#define CP_COMMIT() asm volatile("cp.async.commit_group;\n" ::: "memory")
#define CP_WAIT1()  asm volatile("cp.async.wait_group 1;\n" ::: "memory")

// ---------------- 0. prep: tf32-round + concat weights ----------------
__global__ void k_prep(const float* __restrict__ wc, const float* __restrict__ wl,
                       const float* __restrict__ w1) {
  int j = blockIdx.x;
  int t = threadIdx.x;
  if (j < ROWS_TOT) {
    const float4* src = (j < ROWS_CLS)
        ? (const float4*)(wc + (size_t)j * CIN)
        : (const float4*)(wl + (size_t)(j - ROWS_CLS) * CIN);
    g_A4[(size_t)j * 256 + t] = tf32r4(src[t]);
  } else {
    int r = j - ROWS_TOT;
    g_B4[(size_t)r * 256 + t] = tf32r4(((const float4*)(w1 + (size_t)r * CIN))[t]);
  }
}

// ---------------- 1. transpose h [n,c,s] -> ht [n,s,c], tf32-rounded ----------------
__global__ void k_transpose(const float* __restrict__ h) {
  __shared__ float tile[32][33];
  int n = blockIdx.z;
  int s0 = blockIdx.x * 32, c0 = blockIdx.y * 32;
  int tx = threadIdx.x, ty = threadIdx.y;
  float* ht = (float*)g_ht4;
#pragma unroll
  for (int i = 0; i < 32; i += 8) {
    int c = c0 + ty + i, s = s0 + tx;
    if (c < CIN && s < SPAT) tile[ty + i][tx] = h[((size_t)n * CIN + c) * SPAT + s];
  }
  __syncthreads();
#pragma unroll
  for (int i = 0; i < 32; i += 8) {
    int s = s0 + ty + i, c = c0 + tx;
    if (s < SPAT && c < CIN) ht[((size_t)n * SPAT + s) * CIN + c] = tf32r(tile[tx][ty + i]);
  }
}

// ---------------- 2a. SAT pass 1: prefix along x ----------------
__global__ __launch_bounds__(256) void k_sat1() {
  int by = blockIdx.x;
  int n = blockIdx.y;
  int tid = threadIdx.x;
  float4* satb = g_sat4 + (size_t)n * SATSP * 256;
  if (by == 0) {
    float4 z = make_float4(0.f, 0.f, 0.f, 0.f);
    for (int x = 0; x < SATN; x++) satb[(size_t)x * 256 + tid] = z;
    return;
  }
  int y = by - 1;
  const float4* src = g_ht4 + ((size_t)n * SPAT + y * WW) * 256 + tid;
  float4* dst = satb + (size_t)(by * SATN) * 256 + tid;
  float4 acc = make_float4(0.f, 0.f, 0.f, 0.f);
  dst[0] = acc;
#pragma unroll 5
  for (int x = 0; x < WW; x++) {
    float4 v = src[(size_t)x * 256];
    acc.x += v.x; acc.y += v.y; acc.z += v.z; acc.w += v.w;
    dst[(size_t)(x + 1) * 256] = acc;
  }
}

// ---------------- 2b. SAT pass 2: prefix along y (in place) ----------------
__global__ __launch_bounds__(256) void k_sat2() {
  int x = blockIdx.x;
  int n = blockIdx.y;
  int tid = threadIdx.x;
  float4* p = g_sat4 + ((size_t)n * SATSP + x) * 256 + tid;
  float4 acc = make_float4(0.f, 0.f, 0.f, 0.f);
#pragma unroll 5
  for (int y = 1; y < SATN; y++) {
    float4 v = p[(size_t)(y * SATN) * 256];
    acc.x += v.x; acc.y += v.y; acc.z += v.z; acc.w += v.w;
    p[(size_t)(y * SATN) * 256] = acc;
  }
}

// ---------------- 3. fold GEMM: tf32 mma, cp.async 3-stage pipeline ----------------
// W[j,c] = sum_o A[j,o]*B[o,c].  KT=16, block 64x128, grid (8,20).
#define KT 16
#define NKT (CIN / KT)
#define APAD 20
#define BPAD 132
__global__ __launch_bounds__(256) void k_fold_mma(int dummy) {
  __shared__ float As[3][64][APAD];
  __shared__ float Bs[3][KT][BPAD];
  int t = threadIdx.x;
  int warp = t >> 5, lane = t & 31;
  int n0 = blockIdx.x * 128;
  int m0 = blockIdx.y * 64;
  int warpM = warp >> 2, warpN = warp & 3;     // 2 x 4
  int mb = warpM * 32, nb = warpN * 32;
  int lg = lane >> 2;      // 0..7
  int lt = lane & 3;       // 0..3

  const float* A = (const float*)g_A4;
  const float* B = (const float*)g_B4;

  // per-thread load coords
  int a_row = t >> 2;              // 0..63
  int a_kq = (t & 3) << 2;         // 0,4,8,12
  int a_gm = m0 + a_row;
  int a_ok = (a_gm < ROWS_TOT) ? 16 : 0;
  const float* a_src0 = A + (size_t)(a_ok ? a_gm : 0) * CIN + a_kq;

  float c0[2][4], c1[2][4], c2[2][4], c3[2][4];
#pragma unroll
  for (int i = 0; i < 2; i++)
#pragma unroll
    for (int j = 0; j < 4; j++) { c0[i][j] = c1[i][j] = c2[i][j] = c3[i][j] = 0.f; }

  auto load_tile = [&](int kt, int st) {
    int k0 = kt * KT;
    cpa16(&As[st][a_row][a_kq], a_src0 + k0, a_ok);
#pragma unroll
    for (int i = 0; i < 2; i++) {
      int idx = i * 256 + t;
      int kr = idx >> 5;            // 0..15
      int nq = (idx & 31) << 2;     // 0..124
      cpa16(&Bs[st][kr][nq], B + (size_t)(k0 + kr) * CIN + n0 + nq, 16);
    }
  };

  load_tile(0, 0); CP_COMMIT();
  load_tile(1, 1); CP_COMMIT();

  for (int kt = 0; kt < NKT; kt++) {
    int st = kt % 3;
    CP_WAIT1();
    __syncthreads();
#pragma unroll
    for (int ks = 0; ks < 2; ks++) {
      int kc = ks << 3;
      uint32_t a[2][4];
#pragma unroll
      for (int ms = 0; ms < 2; ms++) {
        int row = mb + (ms << 4) + lg;
        a[ms][0] = __float_as_uint(As[st][row][kc + lt]);
        a[ms][1] = __float_as_uint(As[st][row + 8][kc + lt]);
        a[ms][2] = __float_as_uint(As[st][row][kc + 4 + lt]);
        a[ms][3] = __float_as_uint(As[st][row + 8][kc + 4 + lt]);
      }
      uint32_t b[4][2];
#pragma unroll
      for (int ns = 0; ns < 4; ns++) {
        int col = nb + (ns << 3) + lg;
        b[ns][0] = __float_as_uint(Bs[st][kc + lt][col]);
        b[ns][1] = __float_as_uint(Bs[st][kc + 4 + lt][col]);
      }
#pragma unroll
      for (int ms = 0; ms < 2; ms++)
#pragma unroll
        for (int ns = 0; ns < 4; ns++) {
          asm volatile(
            "mma.sync.aligned.m16n8k8.row.col.f32.tf32.tf32.f32 "
            "{%0,%1,%2,%3}, {%4,%5,%6,%7}, {%8,%9}, {%0,%1,%2,%3};"
            : "+f"(c0[ms][ns]), "+f"(c1[ms][ns]), "+f"(c2[ms][ns]), "+f"(c3[ms][ns])
            : "r"(a[ms][0]), "r"(a[ms][1]), "r"(a[ms][2]), "r"(a[ms][3]),
              "r"(b[ns][0]), "r"(b[ns][1]));
        }
    }
    if (kt + 2 < NKT) load_tile(kt + 2, (kt + 2) % 3);
    CP_COMMIT();
  }

  // epilogue: write tf32-rounded W (consumed by tf32 pgemm)
  float* W = (float*)g_W4;
#pragma unroll
  for (int ms = 0; ms < 2; ms++) {
    int gr = m0 + mb + (ms << 4) + lg;
#pragma unroll
    for (int ns = 0; ns < 4; ns++) {
      int gc = n0 + nb + (ns << 3) + (lt << 1);
      if (gr < ROWS_TOT)
        *(float2*)(W + (size_t)gr * CIN + gc) =
            make_float2(tf32r(c0[ms][ns]), tf32r(c1[ms][ns]));
      if (gr + 8 < ROWS_TOT)
        *(float2*)(W + (size_t)(gr + 8) * CIN + gc) =
            make_float2(tf32r(c2[ms][ns]), tf32r(c3[ms][ns]));
    }
  }
}

// ---------------- 4. folded bias ----------------
__global__ void k_bias(const float* __restrict__ wc, const float* __restrict__ wl,
                       const float* __restrict__ bc, const float* __restrict__ bl,
                       const float* __restrict__ b1) {
  int gw = (blockIdx.x * blockDim.x + threadIdx.x) >> 5;
  int lane = threadIdx.x & 31;
  if (gw >= ROWS_TOT) return;
  const float* row = (gw < ROWS_CLS) ? (wc + (size_t)gw * CIN)
                                     : (wl + (size_t)(gw - ROWS_CLS) * CIN);
  float s = 0.f;
  for (int o = lane; o < CIN; o += 32) s += row[o] * b1[o];
#pragma unroll
  for (int off = 16; off; off >>= 1) s += __shfl_xor_sync(0xffffffffu, s, off);
  if (lane == 0) {
    float base = (gw < ROWS_CLS) ? bc[gw] : bl[gw - ROWS_CLS];
    g_bias[gw] = base + s;
  }
}

// ---------------- roi geometry: XLA semantics (byte-identical to passing rounds) ----
__device__ __forceinline__ void roi_geom(const float* __restrict__ rois, int r, int p, int q,
                                         int& hs, int& he, int& ws, int& we) {
  float x1 = rois[4 * r + 0], y1 = rois[4 * r + 1];
  float x2 = rois[4 * r + 2], y2 = rois[4 * r + 3];
  float sw = __fmul_rn(rintf(x1), 0.0625f);
  float sh = __fmul_rn(rintf(y1), 0.0625f);
  float ew = __fmul_rn(rintf(__fadd_rn(x2, 1.0f)), 0.0625f);
  float eh = __fmul_rn(rintf(__fadd_rn(y2, 1.0f)), 0.0625f);
  float rw = fmaxf(__fadd_rn(ew, -sw), 0.1f);
  float rh = fmaxf(__fadd_rn(eh, -sh), 0.1f);
  const float RSEV = 1.0f / 7.0f;   // XLA: /7 -> * fl(1/7)
  float bh = __fmul_rn(rh, RSEV);
  float bw = __fmul_rn(rw, RSEV);
  float fp = (float)p, fq = (float)q;
  hs = (int)fminf(fmaxf(floorf(__fadd_rn(__fmul_rn(fp, bh), sh)), 0.f), 50.f);
  he = (int)fminf(fmaxf(ceilf(__fadd_rn(__fmul_rn(__fadd_rn(fp, 1.f), bh), sh)), 0.f), 50.f);
  ws = (int)fminf(fmaxf(floorf(__fadd_rn(__fmul_rn(fq, bw), sw)), 0.f), 50.f);
  we = (int)fminf(fmaxf(ceilf(__fadd_rn(__fmul_rn(__fadd_rn(fq, 1.f), bw), sw)), 0.f), 50.f);
}

__device__ __forceinline__ int row_of(int c, int pq) {
  return (c < NCLS) ? (c * PQN + pq) : (ROWS_CLS + (c - NCLS) * PQN + pq);
}

// ---------------- 5a. pooled vectors: P[pq][r][c] = sat-diff / cnt (tf32) -----------
__global__ __launch_bounds__(256) void k_poolvec(const float* __restrict__ rois,
                                                 const int* __restrict__ ridx) {
  int pq = blockIdx.x;
  int g = blockIdx.y;
  int p = pq / 7, q = pq - p * 7;
  int tid = threadIdx.x;

  for (int rr = 0; rr < 30; rr++) {
    int r = g * 30 + rr;
    int hs, he, ws, we;
    roi_geom(rois, r, p, q, hs, he, ws, we);
    int n = ridx[r];
    int cnt = (he - hs) * (we - ws);
    float rcp = (cnt > 0) ? __fdiv_rn(1.0f, (float)cnt) : 0.0f;

    const float4* sat = g_sat4 + (size_t)n * SATSP * 256 + tid;
    float4 s11 = sat[(size_t)(he * SATN + we) * 256];
    float4 s01 = sat[(size_t)(hs * SATN + we) * 256];
    float4 s10 = sat[(size_t)(he * SATN + ws) * 256];
    float4 s00 = sat[(size_t)(hs * SATN + ws) * 256];
    float4 acc = make_float4(((s11.x - s01.x) - (s10.x - s00.x)) * rcp,
                             ((s11.y - s01.y) - (s10.y - s00.y)) * rcp,
                             ((s11.z - s01.z) - (s10.z - s00.z)) * rcp,
                             ((s11.w - s01.w) - (s10.w - s00.w)) * rcp);
    g_P4[((size_t)pq * RR + r) * 256 + tid] = tf32r4(acc);
    if (tid == 0) g_mask[pq * RR + r] = (cnt > 0) ? 1.0f : 0.0f;
  }
}

// ---------------- 5b. per-pq projection GEMM: S[c, r] = W[c,pq,:] . P[pq][r][:] ------
// M=32 (25 used), N=160 per block, K=1024.  Block 128 thr = 4 warps (n-split).
#define KT2 16
#define NKT2 (CIN / KT2)
__global__ __launch_bounds__(128) void k_pgemm(int dummy) {
  __shared__ float As2[32][APAD];     // [m][k]
  __shared__ float Bs2[160][APAD];    // [n(r)][k]
  int t = threadIdx.x;
  int warp = t >> 5, lane = t & 31;
  int pq = blockIdx.y;
  int n0 = blockIdx.x * 160;
  int nb = warp * 40;
  int lg = lane >> 2, lt = lane & 3;

  const float* W = (const float*)g_W4;
  const float* P = (const float*)g_P4;

  float c0[2][5], c1[2][5], c2[2][5], c3[2][5];
#pragma unroll
  for (int i = 0; i < 2; i++)
#pragma unroll
    for (int j = 0; j < 5; j++) { c0[i][j] = c1[i][j] = c2[i][j] = c3[i][j] = 0.f; }

  for (int kt = 0; kt < NKT2; kt++) {
    int k0 = kt * KT2;
    // A tile: 32 m x 16 k = 128 f4, 1/thread
    {
      int m = t >> 2;
      int kq = (t & 3) << 2;
      float4 v = make_float4(0.f, 0.f, 0.f, 0.f);
      if (m < COMB) v = *(const float4*)(W + (size_t)row_of(m, pq) * CIN + k0 + kq);
      *(float4*)&As2[m][kq] = v;
    }
    // B tile: 160 r x 16 k = 640 f4, 5/thread
#pragma unroll
    for (int i = 0; i < 5; i++) {
      int idx = i * 128 + t;
      int nn = idx >> 2;
      int kq = (idx & 3) << 2;
      float4 v = make_float4(0.f, 0.f, 0.f, 0.f);
      if (n0 + nn < RR)
        v = *(const float4*)(P + ((size_t)pq * RR + n0 + nn) * CIN + k0 + kq);
      *(float4*)&Bs2[nn][kq] = v;
    }
    __syncthreads();
#pragma unroll
    for (int ks = 0; ks < 2; ks++) {
      int kc = ks << 3;
      uint32_t a[2][4];
#pragma unroll
      for (int ms = 0; ms < 2; ms++) {
        int row = (ms << 4) + lg;
        a[ms][0] = __float_as_uint(As2[row][kc + lt]);
        a[ms][1] = __float_as_uint(As2[row + 8][kc + lt]);
        a[ms][2] = __float_as_uint(As2[row][kc + 4 + lt]);
        a[ms][3] = __float_as_uint(As2[row + 8][kc + 4 + lt]);
      }
      uint32_t b[5][2];
#pragma unroll
      for (int ns = 0; ns < 5; ns++) {
        int col = nb + (ns << 3) + lg;
        b[ns][0] = __float_as_uint(Bs2[col][kc + lt]);
        b[ns][1] = __float_as_uint(Bs2[col][kc + 4 + lt]);
      }
#pragma unroll
      for (int ms = 0; ms < 2; ms++)
#pragma unroll
        for (int ns = 0; ns < 5; ns++) {
          asm volatile(
            "mma.sync.aligned.m16n8k8.row.col.f32.tf32.tf32.f32 "
            "{%0,%1,%2,%3}, {%4,%5,%6,%7}, {%8,%9}, {%0,%1,%2,%3};"
            : "+f"(c0[ms][ns]), "+f"(c1[ms][ns]), "+f"(c2[ms][ns]), "+f"(c3[ms][ns])
            : "r"(a[ms][0]), "r"(a[ms][1]), "r"(a[ms][2]), "r"(a[ms][3]),
              "r"(b[ns][0]), "r"(b[ns][1]));
        }
    }
    __syncthreads();
  }

  // epilogue: val = (acc + bias) * mask; scatter to g_scr[(r*25+c)*49+pq]
#pragma unroll
  for (int ms = 0; ms < 2; ms++) {
    int m_lo = (ms << 4) + lg;
    int m_hi = m_lo + 8;
    float b_lo = (m_lo < COMB) ? g_bias[row_of(m_lo, pq)] : 0.f;
    float b_hi = (m_hi < COMB) ? g_bias[row_of(m_hi, pq)] : 0.f;
#pragma unroll
    for (int ns = 0; ns < 5; ns++) {
      int r0 = n0 + nb + (ns << 3) + (lt << 1);
#pragma unroll
      for (int rr = 0; rr < 2; rr++) {
        int r = r0 + rr;
        if (r >= RR) continue;
        float mk = g_mask[pq * RR + r];
        if (m_lo < COMB) {
          float v = rr ? c1[ms][ns] : c0[ms][ns];
          g_scr[((size_t)r * COMB + m_lo) * PQN + pq] = (v + b_lo) * mk;
        }
        if (m_hi < COMB) {
          float v = rr ? c3[ms][ns] : c2[ms][ns];
          g_scr[((size_t)r * COMB + m_hi) * PQN + pq] = (v + b_hi) * mk;
        }
      }
    }
  }
}

// ---------------- 6. reduce: mean over 49 bins = sum * fl(1/49) ----------------
__global__ void k_reduce(float* __restrict__ out) {
  int idx = blockIdx.x * blockDim.x + threadIdx.x;
  if (idx >= RR * COMB) return;
  int r = idx / COMB, c = idx - r * COMB;
  const float* src = g_scr + (size_t)idx * PQN;
  float s = 0.f;
#pragma unroll
  for (int pq = 0; pq < PQN; pq++) s += src[pq];
  float mean = __fmul_rn(s, 1.0f / 49.0f);
  if (c < NCLS) out[r * NCLS + c] = mean;                  // roi_score [300,21]
  else out[RR * NCLS + r * 4 + (c - NCLS)] = mean;         // roi_locs  [300,4]
}

// ---------------- launch ----------------
extern "C" void kernel_launch(void* const* d_in, const int* in_sizes, int n_in,
                              void* d_out, int out_size) {
  const float* h    = (const float*)d_in[0];
  const float* rois = (const float*)d_in[1];
  const int*   ridx = (const int*)d_in[2];
  const float* w1   = (const float*)d_in[3];
  const float* b1   = (const float*)d_in[4];
  const float* wc   = (const float*)d_in[5];
  const float* bc   = (const float*)d_in[6];
  const float* wl   = (const float*)d_in[7];
  const float* bl   = (const float*)d_in[8];
  float* out = (float*)d_out;

  k_prep<<<ROWS_TOT + CIN, 256>>>(wc, wl, w1);
  k_transpose<<<dim3((SPAT + 31) / 32, CIN / 32, NB), dim3(32, 8)>>>(h);
  k_fold_mma<<<dim3(CIN / 128, (ROWS_TOT + 63) / 64), 256>>>(0);
  k_sat1<<<dim3(SATN, NB), 256>>>();
  k_sat2<<<dim3(SATN, NB), 256>>>();
  k_bias<<<(ROWS_TOT * 32 + 255) / 256, 256>>>(wc, wl, bc, bl, b1);
  k_poolvec<<<dim3(PQN, 10), 256>>>(rois, ridx);
  k_pgemm<<<dim3(2, PQN), 128>>>(0);
  k_reduce<<<(RR * COMB + 255) / 256, 256>>>(out);
}

// round 11
// speedup vs baseline: 1.3598x; 1.3598x over previous
#include <cuda_runtime.h>
#include <cstdint>

#define NB 2
#define CIN 1024
#define HH 50
#define WW 50
#define SPAT 2500
#define SATN 51
#define SATSP (SATN * SATN)
#define RR 300
#define PQN 49
#define NCLS 21
#define ROWS_CLS 1029
#define ROWS_TOT 1225
#define COMB 25

// ---------------- scratch (static device memory; no allocations) ----------------
__device__ float4 g_ht4[(size_t)NB * SPAT * (CIN / 4)];   // tf32(h) channel-last
__device__ float4 g_sat4[(size_t)NB * SATSP * (CIN / 4)]; // SAT
__device__ float4 g_A4[(size_t)ROWS_TOT * (CIN / 4)];     // tf32(wc‖wl)
__device__ float4 g_B4[(size_t)CIN * (CIN / 4)];          // tf32(w1)
__device__ float4 g_W4[(size_t)ROWS_TOT * (CIN / 4)];     // folded weights (tf32 values)
__device__ float  g_bias[ROWS_TOT];                       // folded bias
__device__ float  g_scr[(size_t)RR * COMB * PQN];         // per-(roi,c,pq) values

// fp32 -> tf32-rounded fp32
__device__ __forceinline__ float tf32r(float x) {
  unsigned u;
  asm("cvt.rna.tf32.f32 %0, %1;" : "=r"(u) : "f"(x));
  return __uint_as_float(u);
}
__device__ __forceinline__ float4 tf32r4(float4 v) {
  return make_float4(tf32r(v.x), tf32r(v.y), tf32r(v.z), tf32r(v.w));
}

// cp.async helpers
__device__ __forceinline__ void cpa16(void* smem, const void* gmem, int srcsz) {
  uint32_t s = (uint32_t)__cvta_generic_to_shared(smem);
  asm volatile("cp.async.cg.shared.global [%0], [%1], 16, %2;\n"
               :: "r"(s), "l"(gmem), "r"(srcsz));
}
#define CP_COMMIT() asm volatile("cp.async.commit_group;\n" ::: "memory")
#define CP_WAIT1()  asm volatile("cp.async.wait_group 1;\n" ::: "memory")

// ---------------- 0. prep: tf32-round + concat weights ----------------
__global__ void k_prep(const float* __restrict__ wc, const float* __restrict__ wl,
                       const float* __restrict__ w1) {
  int j = blockIdx.x;
  int t = threadIdx.x;
  if (j < ROWS_TOT) {
    const float4* src = (j < ROWS_CLS)
        ? (const float4*)(wc + (size_t)j * CIN)
        : (const float4*)(wl + (size_t)(j - ROWS_CLS) * CIN);
    g_A4[(size_t)j * 256 + t] = tf32r4(src[t]);
  } else {
    int r = j - ROWS_TOT;
    g_B4[(size_t)r * 256 + t] = tf32r4(((const float4*)(w1 + (size_t)r * CIN))[t]);
  }
}

// ---------------- 1. transpose h [n,c,s] -> ht [n,s,c], tf32-rounded ----------------
__global__ void k_transpose(const float* __restrict__ h) {
  __shared__ float tile[32][33];
  int n = blockIdx.z;
  int s0 = blockIdx.x * 32, c0 = blockIdx.y * 32;
  int tx = threadIdx.x, ty = threadIdx.y;
  float* ht = (float*)g_ht4;
#pragma unroll
  for (int i = 0; i < 32; i += 8) {
    int c = c0 + ty + i, s = s0 + tx;
    if (c < CIN && s < SPAT) tile[ty + i][tx] = h[((size_t)n * CIN + c) * SPAT + s];
  }
  __syncthreads();
#pragma unroll
  for (int i = 0; i < 32; i += 8) {
    int s = s0 + ty + i, c = c0 + tx;
    if (s < SPAT && c < CIN) ht[((size_t)n * SPAT + s) * CIN + c] = tf32r(tile[tx][ty + i]);
  }
}

// ---------------- 2a. SAT pass 1: prefix along x (prefetched) ----------------
__global__ __launch_bounds__(256) void k_sat1() {
  int by = blockIdx.x;
  int n = blockIdx.y;
  int tid = threadIdx.x;
  float4* satb = g_sat4 + (size_t)n * SATSP * 256;
  if (by == 0) {
    float4 z = make_float4(0.f, 0.f, 0.f, 0.f);
    for (int x = 0; x < SATN; x++) satb[(size_t)x * 256 + tid] = z;
    return;
  }
  int y = by - 1;
  const float4* src = g_ht4 + ((size_t)n * SPAT + y * WW) * 256 + tid;
  float4* dst = satb + (size_t)(by * SATN) * 256 + tid;
  float4 acc = make_float4(0.f, 0.f, 0.f, 0.f);
  dst[0] = acc;
  float4 buf[4];
#pragma unroll
  for (int i = 0; i < 4; i++) buf[i] = src[(size_t)i * 256];
  for (int x0 = 0; x0 < 48; x0 += 4) {
#pragma unroll
    for (int j = 0; j < 4; j++) {
      float4 v = buf[j];
      if (x0 + 4 + j < WW) buf[j] = src[(size_t)(x0 + 4 + j) * 256];
      acc.x += v.x; acc.y += v.y; acc.z += v.z; acc.w += v.w;
      dst[(size_t)(x0 + 1 + j) * 256] = acc;
    }
  }
#pragma unroll
  for (int j = 0; j < 2; j++) {     // x = 48, 49
    float4 v = buf[j];
    acc.x += v.x; acc.y += v.y; acc.z += v.z; acc.w += v.w;
    dst[(size_t)(49 + j) * 256] = acc;
  }
}

// ---------------- 2b. SAT pass 2: prefix along y, in place (prefetched) -------------
__global__ __launch_bounds__(256) void k_sat2() {
  int x = blockIdx.x;
  int n = blockIdx.y;
  int tid = threadIdx.x;
  float4* p = g_sat4 + ((size_t)n * SATSP + x) * 256 + tid;
  const size_t RS = (size_t)SATN * 256;
  float4 acc = make_float4(0.f, 0.f, 0.f, 0.f);
  float4 buf[4];
#pragma unroll
  for (int i = 0; i < 4; i++) buf[i] = p[(size_t)(1 + i) * RS];
  for (int y0 = 0; y0 < 48; y0 += 4) {
#pragma unroll
    for (int j = 0; j < 4; j++) {
      float4 v = buf[j];
      if (y0 + 5 + j <= 50) buf[j] = p[(size_t)(y0 + 5 + j) * RS];
      acc.x += v.x; acc.y += v.y; acc.z += v.z; acc.w += v.w;
      p[(size_t)(y0 + 1 + j) * RS] = acc;
    }
  }
#pragma unroll
  for (int j = 0; j < 2; j++) {     // y = 49, 50
    float4 v = buf[j];
    acc.x += v.x; acc.y += v.y; acc.z += v.z; acc.w += v.w;
    p[(size_t)(49 + j) * RS] = acc;
  }
}

// ---------------- 3. fold GEMM: tf32 mma, cp.async 3-stage, 64x64 tiles -------------
// W[j,c] = sum_o A[j,o]*B[o,c].  KT=16, block 64x64, 128 thr, grid (16,20)=320.
#define KT 16
#define NKT (CIN / KT)
#define APAD 20
#define BPAD 68
__global__ __launch_bounds__(128) void k_fold_mma(int dummy) {
  __shared__ float As[3][64][APAD];
  __shared__ float Bs[3][KT][BPAD];
  int t = threadIdx.x;
  int warp = t >> 5, lane = t & 31;
  int n0 = blockIdx.x * 64;
  int m0 = blockIdx.y * 64;
  int warpM = warp >> 1, warpN = warp & 1;     // 2 x 2
  int mb = warpM * 32, nb = warpN * 32;
  int lg = lane >> 2;      // 0..7
  int lt = lane & 3;       // 0..3

  const float* A = (const float*)g_A4;
  const float* B = (const float*)g_B4;

  // A-load coords: 2 float4/thread
  int a_row0 = t >> 2, a_kq0 = (t & 3) << 2;
  int a_row1 = (128 + t) >> 2, a_kq1 = ((128 + t) & 3) << 2;
  int gm0 = m0 + a_row0, gm1 = m0 + a_row1;
  int ok0 = (gm0 < ROWS_TOT) ? 16 : 0;
  int ok1 = (gm1 < ROWS_TOT) ? 16 : 0;
  const float* a_src0 = A + (size_t)(ok0 ? gm0 : 0) * CIN + a_kq0;
  const float* a_src1 = A + (size_t)(ok1 ? gm1 : 0) * CIN + a_kq1;

  float c0[2][4], c1[2][4], c2[2][4], c3[2][4];
#pragma unroll
  for (int i = 0; i < 2; i++)
#pragma unroll
    for (int j = 0; j < 4; j++) { c0[i][j] = c1[i][j] = c2[i][j] = c3[i][j] = 0.f; }

  auto load_tile = [&](int kt, int st) {
    int k0 = kt * KT;
    cpa16(&As[st][a_row0][a_kq0], a_src0 + k0, ok0);
    cpa16(&As[st][a_row1][a_kq1], a_src1 + k0, ok1);
#pragma unroll
    for (int i = 0; i < 2; i++) {
      int idx = i * 128 + t;
      int kr = idx >> 4;            // 0..15
      int nq = (idx & 15) << 2;     // 0..60
      cpa16(&Bs[st][kr][nq], B + (size_t)(k0 + kr) * CIN + n0 + nq, 16);
    }
  };

  load_tile(0, 0); CP_COMMIT();
  load_tile(1, 1); CP_COMMIT();

  for (int kt = 0; kt < NKT; kt++) {
    int st = kt % 3;
    CP_WAIT1();
    __syncthreads();
#pragma unroll
    for (int ks = 0; ks < 2; ks++) {
      int kc = ks << 3;
      uint32_t a[2][4];
#pragma unroll
      for (int ms = 0; ms < 2; ms++) {
        int row = mb + (ms << 4) + lg;
        a[ms][0] = __float_as_uint(As[st][row][kc + lt]);
        a[ms][1] = __float_as_uint(As[st][row + 8][kc + lt]);
        a[ms][2] = __float_as_uint(As[st][row][kc + 4 + lt]);
        a[ms][3] = __float_as_uint(As[st][row + 8][kc + 4 + lt]);
      }
      uint32_t b[4][2];
#pragma unroll
      for (int ns = 0; ns < 4; ns++) {
        int col = nb + (ns << 3) + lg;
        b[ns][0] = __float_as_uint(Bs[st][kc + lt][col]);
        b[ns][1] = __float_as_uint(Bs[st][kc + 4 + lt][col]);
      }
#pragma unroll
      for (int ms = 0; ms < 2; ms++)
#pragma unroll
        for (int ns = 0; ns < 4; ns++) {
          asm volatile(
            "mma.sync.aligned.m16n8k8.row.col.f32.tf32.tf32.f32 "
            "{%0,%1,%2,%3}, {%4,%5,%6,%7}, {%8,%9}, {%0,%1,%2,%3};"
            : "+f"(c0[ms][ns]), "+f"(c1[ms][ns]), "+f"(c2[ms][ns]), "+f"(c3[ms][ns])
            : "r"(a[ms][0]), "r"(a[ms][1]), "r"(a[ms][2]), "r"(a[ms][3]),
              "r"(b[ns][0]), "r"(b[ns][1]));
        }
    }
    if (kt + 2 < NKT) load_tile(kt + 2, (kt + 2) % 3);
    CP_COMMIT();
  }

  float* W = (float*)g_W4;
#pragma unroll
  for (int ms = 0; ms < 2; ms++) {
    int gr = m0 + mb + (ms << 4) + lg;
#pragma unroll
    for (int ns = 0; ns < 4; ns++) {
      int gc = n0 + nb + (ns << 3) + (lt << 1);
      if (gr < ROWS_TOT)
        *(float2*)(W + (size_t)gr * CIN + gc) =
            make_float2(tf32r(c0[ms][ns]), tf32r(c1[ms][ns]));
      if (gr + 8 < ROWS_TOT)
        *(float2*)(W + (size_t)(gr + 8) * CIN + gc) =
            make_float2(tf32r(c2[ms][ns]), tf32r(c3[ms][ns]));
    }
  }
}

// ---------------- 4. folded bias ----------------
__global__ void k_bias(const float* __restrict__ wc, const float* __restrict__ wl,
                       const float* __restrict__ bc, const float* __restrict__ bl,
                       const float* __restrict__ b1) {
  int gw = (blockIdx.x * blockDim.x + threadIdx.x) >> 5;
  int lane = threadIdx.x & 31;
  if (gw >= ROWS_TOT) return;
  const float* row = (gw < ROWS_CLS) ? (wc + (size_t)gw * CIN)
                                     : (wl + (size_t)(gw - ROWS_CLS) * CIN);
  float s = 0.f;
  for (int o = lane; o < CIN; o += 32) s += row[o] * b1[o];
#pragma unroll
  for (int off = 16; off; off >>= 1) s += __shfl_xor_sync(0xffffffffu, s, off);
  if (lane == 0) {
    float base = (gw < ROWS_CLS) ? bc[gw] : bl[gw - ROWS_CLS];
    g_bias[gw] = base + s;
  }
}

// ---------------- roi geometry: XLA semantics (byte-identical to passing rounds) ----
__device__ __forceinline__ void roi_geom(const float* __restrict__ rois, int r, int p, int q,
                                         int& hs, int& he, int& ws, int& we) {
  float x1 = rois[4 * r + 0], y1 = rois[4 * r + 1];
  float x2 = rois[4 * r + 2], y2 = rois[4 * r + 3];
  float sw = __fmul_rn(rintf(x1), 0.0625f);
  float sh = __fmul_rn(rintf(y1), 0.0625f);
  float ew = __fmul_rn(rintf(__fadd_rn(x2, 1.0f)), 0.0625f);
  float eh = __fmul_rn(rintf(__fadd_rn(y2, 1.0f)), 0.0625f);
  float rw = fmaxf(__fadd_rn(ew, -sw), 0.1f);
  float rh = fmaxf(__fadd_rn(eh, -sh), 0.1f);
  const float RSEV = 1.0f / 7.0f;   // XLA: /7 -> * fl(1/7)
  float bh = __fmul_rn(rh, RSEV);
  float bw = __fmul_rn(rw, RSEV);
  float fp = (float)p, fq = (float)q;
  hs = (int)fminf(fmaxf(floorf(__fadd_rn(__fmul_rn(fp, bh), sh)), 0.f), 50.f);
  he = (int)fminf(fmaxf(ceilf(__fadd_rn(__fmul_rn(__fadd_rn(fp, 1.f), bh), sh)), 0.f), 50.f);
  ws = (int)fminf(fmaxf(floorf(__fadd_rn(__fmul_rn(fq, bw), sw)), 0.f), 50.f);
  we = (int)fminf(fmaxf(ceilf(__fadd_rn(__fmul_rn(__fadd_rn(fq, 1.f), bw), sw)), 0.f), 50.f);
}

__device__ __forceinline__ int row_of(int c, int pq) {
  return (c < NCLS) ? (c * PQN + pq) : (ROWS_CLS + (c - NCLS) * PQN + pq);
}

// ---------------- 5. fused pool + projection (P in smem, tf32 mma) ------------------
// grid (49 pq, 19 chunks of 16 rois), 128 threads. Dynamic smem: Ps[16][1028].
#define CHUNK 16
#define PSTR 1028
__global__ __launch_bounds__(128) void k_poolproj(const float* __restrict__ rois,
                                                  const int* __restrict__ ridx) {
  extern __shared__ float Ps[];        // [CHUNK][PSTR]
  __shared__ float As2[32][APAD];
  __shared__ float biasS[32];
  __shared__ float maskS[CHUNK];
  int pq = blockIdx.x, g = blockIdx.y;
  int p = pq / 7, q = pq - p * 7;
  int t = threadIdx.x;
  int warp = t >> 5, lane = t & 31;
  int lg = lane >> 2, lt = lane & 3;

  if (t < 32) biasS[t] = (t < COMB) ? g_bias[row_of(t, pq)] : 0.f;

  // Phase A: pooled vectors into smem (tf32-rounded; identical numerics to R10)
  for (int rr = 0; rr < CHUNK; rr++) {
    int r = g * CHUNK + rr;
    if (r < RR) {
      int hs, he, ws, we;
      roi_geom(rois, r, p, q, hs, he, ws, we);
      int n = ridx[r];
      int cnt = (he - hs) * (we - ws);
      float rcp = (cnt > 0) ? __fdiv_rn(1.0f, (float)cnt) : 0.0f;
      const float4* sat = g_sat4 + (size_t)n * SATSP * 256;
#pragma unroll
      for (int sgm = 0; sgm < 2; sgm++) {
        int c4 = t + sgm * 128;
        float4 s11 = sat[(size_t)(he * SATN + we) * 256 + c4];
        float4 s01 = sat[(size_t)(hs * SATN + we) * 256 + c4];
        float4 s10 = sat[(size_t)(he * SATN + ws) * 256 + c4];
        float4 s00 = sat[(size_t)(hs * SATN + ws) * 256 + c4];
        float4 acc = make_float4(((s11.x - s01.x) - (s10.x - s00.x)) * rcp,
                                 ((s11.y - s01.y) - (s10.y - s00.y)) * rcp,
                                 ((s11.z - s01.z) - (s10.z - s00.z)) * rcp,
                                 ((s11.w - s01.w) - (s10.w - s00.w)) * rcp);
        *(float4*)&Ps[rr * PSTR + (c4 << 2)] = tf32r4(acc);
      }
      if (t == 0) maskS[rr] = (cnt > 0) ? 1.0f : 0.0f;
    } else {
      float4 z = make_float4(0.f, 0.f, 0.f, 0.f);
#pragma unroll
      for (int sgm = 0; sgm < 2; sgm++)
        *(float4*)&Ps[rr * PSTR + ((t + sgm * 128) << 2)] = z;
      if (t == 0) maskS[rr] = 0.f;
    }
  }
  __syncthreads();

  // Phase B: S[m, roi] = W[row_of(m,pq), :] . P[roi, :]   (M=32, N=16, K=1024)
  int ms = warp >> 1, ns = warp & 1;   // each warp owns one (ms, ns) 16x8 block
  float c0 = 0.f, c1 = 0.f, c2 = 0.f, c3 = 0.f;
  const float* W = (const float*)g_W4;
  int am = t >> 2, akq = (t & 3) << 2;
  const float* aw = (am < COMB) ? (W + (size_t)row_of(am, pq) * CIN + akq) : 0;

  for (int kt = 0; kt < 64; kt++) {
    int k0 = kt * KT;
    float4 v = aw ? *(const float4*)(aw + k0) : make_float4(0.f, 0.f, 0.f, 0.f);
    __syncthreads();
    *(float4*)&As2[am][akq] = v;
    __syncthreads();
#pragma unroll
    for (int ks = 0; ks < 2; ks++) {
      int kc = ks << 3;
      int row = (ms << 4) + lg;
      uint32_t a0 = __float_as_uint(As2[row][kc + lt]);
      uint32_t a1 = __float_as_uint(As2[row + 8][kc + lt]);
      uint32_t a2 = __float_as_uint(As2[row][kc + 4 + lt]);
      uint32_t a3 = __float_as_uint(As2[row + 8][kc + 4 + lt]);
      int col = (ns << 3) + lg;
      uint32_t b0 = __float_as_uint(Ps[col * PSTR + k0 + kc + lt]);
      uint32_t b1 = __float_as_uint(Ps[col * PSTR + k0 + kc + 4 + lt]);
      asm volatile(
        "mma.sync.aligned.m16n8k8.row.col.f32.tf32.tf32.f32 "
        "{%0,%1,%2,%3}, {%4,%5,%6,%7}, {%8,%9}, {%0,%1,%2,%3};"
        : "+f"(c0), "+f"(c1), "+f"(c2), "+f"(c3)
        : "r"(a0), "r"(a1), "r"(a2), "r"(a3), "r"(b0), "r"(b1));
    }
  }

  // epilogue
  int m_lo = (ms << 4) + lg, m_hi = m_lo + 8;
  int col0 = (ns << 3) + (lt << 1);
  float b_lo = biasS[m_lo], b_hi = biasS[m_hi];
#pragma unroll
  for (int rr2 = 0; rr2 < 2; rr2++) {
    int col = col0 + rr2;
    int r = g * CHUNK + col;
    if (r < RR) {
      float mk = maskS[col];
      if (m_lo < COMB)
        g_scr[((size_t)r * COMB + m_lo) * PQN + pq] = ((rr2 ? c1 : c0) + b_lo) * mk;
      if (m_hi < COMB)
        g_scr[((size_t)r * COMB + m_hi) * PQN + pq] = ((rr2 ? c3 : c2) + b_hi) * mk;
    }
  }
}

// ---------------- 6. reduce: mean over 49 bins = sum * fl(1/49) ----------------
__global__ void k_reduce(float* __restrict__ out) {
  int idx = blockIdx.x * blockDim.x + threadIdx.x;
  if (idx >= RR * COMB) return;
  int r = idx / COMB, c = idx - r * COMB;
  const float* src = g_scr + (size_t)idx * PQN;
  float s = 0.f;
#pragma unroll
  for (int pq = 0; pq < PQN; pq++) s += src[pq];
  float mean = __fmul_rn(s, 1.0f / 49.0f);
  if (c < NCLS) out[r * NCLS + c] = mean;                  // roi_score [300,21]
  else out[RR * NCLS + r * 4 + (c - NCLS)] = mean;         // roi_locs  [300,4]
}

// ---------------- launch ----------------
extern "C" void kernel_launch(void* const* d_in, const int* in_sizes, int n_in,
                              void* d_out, int out_size) {
  const float* h    = (const float*)d_in[0];
  const float* rois = (const float*)d_in[1];
  const int*   ridx = (const int*)d_in[2];
  const float* w1   = (const float*)d_in[3];
  const float* b1   = (const float*)d_in[4];
  const float* wc   = (const float*)d_in[5];
  const float* bc   = (const float*)d_in[6];
  const float* wl   = (const float*)d_in[7];
  const float* bl   = (const float*)d_in[8];
  float* out = (float*)d_out;

  const int PSMEM = CHUNK * PSTR * 4;   // 65792 B dynamic
  cudaFuncSetAttribute(k_poolproj, cudaFuncAttributeMaxDynamicSharedMemorySize, PSMEM);

  k_prep<<<ROWS_TOT + CIN, 256>>>(wc, wl, w1);
  k_transpose<<<dim3((SPAT + 31) / 32, CIN / 32, NB), dim3(32, 8)>>>(h);
  k_fold_mma<<<dim3(CIN / 64, (ROWS_TOT + 63) / 64), 128>>>(0);
  k_sat1<<<dim3(SATN, NB), 256>>>();
  k_sat2<<<dim3(SATN, NB), 256>>>();
  k_bias<<<(ROWS_TOT * 32 + 255) / 256, 256>>>(wc, wl, bc, bl, b1);
  k_poolproj<<<dim3(PQN, (RR + CHUNK - 1) / CHUNK), 128, PSMEM>>>(rois, ridx);
  k_reduce<<<(RR * COMB + 255) / 256, 256>>>(out);
}

// round 12
// speedup vs baseline: 1.6262x; 1.1960x over previous
#include <cuda_runtime.h>
#include <cstdint>

#define NB 2
#define CIN 1024
#define HH 50
#define WW 50
#define SPAT 2500
#define SATN 51
#define SATSP (SATN * SATN)
#define RR 300
#define PQN 49
#define NCLS 21
#define ROWS_CLS 1029
#define ROWS_TOT 1225
#define COMB 25

// ---------------- scratch (static device memory; no allocations) ----------------
__device__ float4 g_ht4[(size_t)NB * SPAT * (CIN / 4)];   // tf32(h) channel-last
__device__ float4 g_sat4[(size_t)NB * SATSP * (CIN / 4)]; // SAT
__device__ float4 g_A4[(size_t)ROWS_TOT * (CIN / 4)];     // tf32(wc‖wl)
__device__ float4 g_B4[(size_t)CIN * (CIN / 4)];          // tf32(w1)
__device__ float4 g_W4[(size_t)ROWS_TOT * (CIN / 4)];     // folded weights (tf32 values)
__device__ float  g_bias[ROWS_TOT];                       // folded bias
__device__ float  g_scr[(size_t)RR * COMB * PQN];         // per-(roi,c,pq) values

// fp32 -> tf32-rounded fp32
__device__ __forceinline__ float tf32r(float x) {
  unsigned u;
  asm("cvt.rna.tf32.f32 %0, %1;" : "=r"(u) : "f"(x));
  return __uint_as_float(u);
}
__device__ __forceinline__ float4 tf32r4(float4 v) {
  return make_float4(tf32r(v.x), tf32r(v.y), tf32r(v.z), tf32r(v.w));
}

// cp.async helpers
__device__ __forceinline__ void cpa16(void* smem, const void* gmem, int srcsz) {
  uint32_t s = (uint32_t)__cvta_generic_to_shared(smem);
  asm volatile("cp.async.cg.shared.global [%0], [%1], 16, %2;\n"
               :: "r"(s), "l"(gmem), "r"(srcsz));
}
#define CP_COMMIT() asm volatile("cp.async.commit_group;\n" ::: "memory")
#define CP_WAIT1()  asm volatile("cp.async.wait_group 1;\n" ::: "memory")

// ---------------- 0. prep: tf32-round + concat weights ----------------
__global__ void k_prep(const float* __restrict__ wc, const float* __restrict__ wl,
                       const float* __restrict__ w1) {
  int j = blockIdx.x;
  int t = threadIdx.x;
  if (j < ROWS_TOT) {
    const float4* src = (j < ROWS_CLS)
        ? (const float4*)(wc + (size_t)j * CIN)
        : (const float4*)(wl + (size_t)(j - ROWS_CLS) * CIN);
    g_A4[(size_t)j * 256 + t] = tf32r4(src[t]);
  } else {
    int r = j - ROWS_TOT;
    g_B4[(size_t)r * 256 + t] = tf32r4(((const float4*)(w1 + (size_t)r * CIN))[t]);
  }
}

// ---------------- 1. transpose h [n,c,s] -> ht [n,s,c], tf32-rounded ----------------
__global__ void k_transpose(const float* __restrict__ h) {
  __shared__ float tile[32][33];
  int n = blockIdx.z;
  int s0 = blockIdx.x * 32, c0 = blockIdx.y * 32;
  int tx = threadIdx.x, ty = threadIdx.y;
  float* ht = (float*)g_ht4;
#pragma unroll
  for (int i = 0; i < 32; i += 8) {
    int c = c0 + ty + i, s = s0 + tx;
    if (c < CIN && s < SPAT) tile[ty + i][tx] = h[((size_t)n * CIN + c) * SPAT + s];
  }
  __syncthreads();
#pragma unroll
  for (int i = 0; i < 32; i += 8) {
    int s = s0 + ty + i, c = c0 + tx;
    if (s < SPAT && c < CIN) ht[((size_t)n * SPAT + s) * CIN + c] = tf32r(tile[tx][ty + i]);
  }
}

// ---------------- 2a. SAT pass 1: prefix along x (8-deep prefetch) ----------------
// grid (51, NB, 2), 128 threads; c4 = z*128 + tid
__global__ __launch_bounds__(128) void k_sat1() {
  int by = blockIdx.x;
  int n = blockIdx.y;
  int c4 = blockIdx.z * 128 + threadIdx.x;
  float4* satb = g_sat4 + (size_t)n * SATSP * 256;
  if (by == 0) {
    float4 z = make_float4(0.f, 0.f, 0.f, 0.f);
    for (int x = 0; x < SATN; x++) satb[(size_t)x * 256 + c4] = z;
    return;
  }
  int y = by - 1;
  const float4* src = g_ht4 + ((size_t)n * SPAT + y * WW) * 256 + c4;
  float4* dst = satb + (size_t)(by * SATN) * 256 + c4;
  float4 acc = make_float4(0.f, 0.f, 0.f, 0.f);
  dst[0] = acc;
  float4 buf[8];
#pragma unroll
  for (int i = 0; i < 8; i++) buf[i] = src[(size_t)i * 256];
  for (int x0 = 0; x0 < 48; x0 += 8) {
#pragma unroll
    for (int j = 0; j < 8; j++) {
      float4 v = buf[j];
      if (x0 + 8 + j < WW) buf[j] = src[(size_t)(x0 + 8 + j) * 256];
      acc.x += v.x; acc.y += v.y; acc.z += v.z; acc.w += v.w;
      dst[(size_t)(x0 + 1 + j) * 256] = acc;
    }
  }
#pragma unroll
  for (int j = 0; j < 2; j++) {     // x = 48, 49
    float4 v = buf[j];
    acc.x += v.x; acc.y += v.y; acc.z += v.z; acc.w += v.w;
    dst[(size_t)(49 + j) * 256] = acc;
  }
}

// ---------------- 2b. SAT pass 2: prefix along y, in place (8-deep prefetch) --------
// grid (51, NB, 2), 128 threads
__global__ __launch_bounds__(128) void k_sat2() {
  int x = blockIdx.x;
  int n = blockIdx.y;
  int c4 = blockIdx.z * 128 + threadIdx.x;
  float4* p = g_sat4 + ((size_t)n * SATSP + x) * 256 + c4;
  const size_t RS = (size_t)SATN * 256;
  float4 acc = make_float4(0.f, 0.f, 0.f, 0.f);
  float4 buf[8];
#pragma unroll
  for (int i = 0; i < 8; i++) buf[i] = p[(size_t)(1 + i) * RS];
  for (int y0 = 0; y0 < 48; y0 += 8) {
#pragma unroll
    for (int j = 0; j < 8; j++) {
      float4 v = buf[j];
      if (y0 + 9 + j <= 50) buf[j] = p[(size_t)(y0 + 9 + j) * RS];
      acc.x += v.x; acc.y += v.y; acc.z += v.z; acc.w += v.w;
      p[(size_t)(y0 + 1 + j) * RS] = acc;
    }
  }
#pragma unroll
  for (int j = 0; j < 2; j++) {     // y = 49, 50
    float4 v = buf[j];
    acc.x += v.x; acc.y += v.y; acc.z += v.z; acc.w += v.w;
    p[(size_t)(49 + j) * RS] = acc;
  }
}

// ---------------- 3. fold GEMM: tf32 mma, cp.async 3-stage, 64x64 tiles -------------
#define KT 16
#define NKT (CIN / KT)
#define APAD 20
#define BPAD 68
__global__ __launch_bounds__(128) void k_fold_mma(int dummy) {
  __shared__ float As[3][64][APAD];
  __shared__ float Bs[3][KT][BPAD];
  int t = threadIdx.x;
  int warp = t >> 5, lane = t & 31;
  int n0 = blockIdx.x * 64;
  int m0 = blockIdx.y * 64;
  int warpM = warp >> 1, warpN = warp & 1;     // 2 x 2
  int mb = warpM * 32, nb = warpN * 32;
  int lg = lane >> 2;      // 0..7
  int lt = lane & 3;       // 0..3

  const float* A = (const float*)g_A4;
  const float* B = (const float*)g_B4;

  int a_row0 = t >> 2, a_kq0 = (t & 3) << 2;
  int a_row1 = (128 + t) >> 2, a_kq1 = ((128 + t) & 3) << 2;
  int gm0 = m0 + a_row0, gm1 = m0 + a_row1;
  int ok0 = (gm0 < ROWS_TOT) ? 16 : 0;
  int ok1 = (gm1 < ROWS_TOT) ? 16 : 0;
  const float* a_src0 = A + (size_t)(ok0 ? gm0 : 0) * CIN + a_kq0;
  const float* a_src1 = A + (size_t)(ok1 ? gm1 : 0) * CIN + a_kq1;

  float c0[2][4], c1[2][4], c2[2][4], c3[2][4];
#pragma unroll
  for (int i = 0; i < 2; i++)
#pragma unroll
    for (int j = 0; j < 4; j++) { c0[i][j] = c1[i][j] = c2[i][j] = c3[i][j] = 0.f; }

  auto load_tile = [&](int kt, int st) {
    int k0 = kt * KT;
    cpa16(&As[st][a_row0][a_kq0], a_src0 + k0, ok0);
    cpa16(&As[st][a_row1][a_kq1], a_src1 + k0, ok1);
#pragma unroll
    for (int i = 0; i < 2; i++) {
      int idx = i * 128 + t;
      int kr = idx >> 4;
      int nq = (idx & 15) << 2;
      cpa16(&Bs[st][kr][nq], B + (size_t)(k0 + kr) * CIN + n0 + nq, 16);
    }
  };

  load_tile(0, 0); CP_COMMIT();
  load_tile(1, 1); CP_COMMIT();

  for (int kt = 0; kt < NKT; kt++) {
    int st = kt % 3;
    CP_WAIT1();
    __syncthreads();
#pragma unroll
    for (int ks = 0; ks < 2; ks++) {
      int kc = ks << 3;
      uint32_t a[2][4];
#pragma unroll
      for (int ms = 0; ms < 2; ms++) {
        int row = mb + (ms << 4) + lg;
        a[ms][0] = __float_as_uint(As[st][row][kc + lt]);
        a[ms][1] = __float_as_uint(As[st][row + 8][kc + lt]);
        a[ms][2] = __float_as_uint(As[st][row][kc + 4 + lt]);
        a[ms][3] = __float_as_uint(As[st][row + 8][kc + 4 + lt]);
      }
      uint32_t b[4][2];
#pragma unroll
      for (int ns = 0; ns < 4; ns++) {
        int col = nb + (ns << 3) + lg;
        b[ns][0] = __float_as_uint(Bs[st][kc + lt][col]);
        b[ns][1] = __float_as_uint(Bs[st][kc + 4 + lt][col]);
      }
#pragma unroll
      for (int ms = 0; ms < 2; ms++)
#pragma unroll
        for (int ns = 0; ns < 4; ns++) {
          asm volatile(
            "mma.sync.aligned.m16n8k8.row.col.f32.tf32.tf32.f32 "
            "{%0,%1,%2,%3}, {%4,%5,%6,%7}, {%8,%9}, {%0,%1,%2,%3};"
            : "+f"(c0[ms][ns]), "+f"(c1[ms][ns]), "+f"(c2[ms][ns]), "+f"(c3[ms][ns])
            : "r"(a[ms][0]), "r"(a[ms][1]), "r"(a[ms][2]), "r"(a[ms][3]),
              "r"(b[ns][0]), "r"(b[ns][1]));
        }
    }
    if (kt + 2 < NKT) load_tile(kt + 2, (kt + 2) % 3);
    CP_COMMIT();
  }

  float* W = (float*)g_W4;
#pragma unroll
  for (int ms = 0; ms < 2; ms++) {
    int gr = m0 + mb + (ms << 4) + lg;
#pragma unroll
    for (int ns = 0; ns < 4; ns++) {
      int gc = n0 + nb + (ns << 3) + (lt << 1);
      if (gr < ROWS_TOT)
        *(float2*)(W + (size_t)gr * CIN + gc) =
            make_float2(tf32r(c0[ms][ns]), tf32r(c1[ms][ns]));
      if (gr + 8 < ROWS_TOT)
        *(float2*)(W + (size_t)(gr + 8) * CIN + gc) =
            make_float2(tf32r(c2[ms][ns]), tf32r(c3[ms][ns]));
    }
  }
}

// ---------------- 4. folded bias ----------------
__global__ void k_bias(const float* __restrict__ wc, const float* __restrict__ wl,
                       const float* __restrict__ bc, const float* __restrict__ bl,
                       const float* __restrict__ b1) {
  int gw = (blockIdx.x * blockDim.x + threadIdx.x) >> 5;
  int lane = threadIdx.x & 31;
  if (gw >= ROWS_TOT) return;
  const float* row = (gw < ROWS_CLS) ? (wc + (size_t)gw * CIN)
                                     : (wl + (size_t)(gw - ROWS_CLS) * CIN);
  float s = 0.f;
  for (int o = lane; o < CIN; o += 32) s += row[o] * b1[o];
#pragma unroll
  for (int off = 16; off; off >>= 1) s += __shfl_xor_sync(0xffffffffu, s, off);
  if (lane == 0) {
    float base = (gw < ROWS_CLS) ? bc[gw] : bl[gw - ROWS_CLS];
    g_bias[gw] = base + s;
  }
}

// ---------------- roi geometry: XLA semantics (byte-identical to passing rounds) ----
__device__ __forceinline__ void roi_geom(const float* __restrict__ rois, int r, int p, int q,
                                         int& hs, int& he, int& ws, int& we) {
  float x1 = rois[4 * r + 0], y1 = rois[4 * r + 1];
  float x2 = rois[4 * r + 2], y2 = rois[4 * r + 3];
  float sw = __fmul_rn(rintf(x1), 0.0625f);
  float sh = __fmul_rn(rintf(y1), 0.0625f);
  float ew = __fmul_rn(rintf(__fadd_rn(x2, 1.0f)), 0.0625f);
  float eh = __fmul_rn(rintf(__fadd_rn(y2, 1.0f)), 0.0625f);
  float rw = fmaxf(__fadd_rn(ew, -sw), 0.1f);
  float rh = fmaxf(__fadd_rn(eh, -sh), 0.1f);
  const float RSEV = 1.0f / 7.0f;   // XLA: /7 -> * fl(1/7)
  float bh = __fmul_rn(rh, RSEV);
  float bw = __fmul_rn(rw, RSEV);
  float fp = (float)p, fq = (float)q;
  hs = (int)fminf(fmaxf(floorf(__fadd_rn(__fmul_rn(fp, bh), sh)), 0.f), 50.f);
  he = (int)fminf(fmaxf(ceilf(__fadd_rn(__fmul_rn(__fadd_rn(fp, 1.f), bh), sh)), 0.f), 50.f);
  ws = (int)fminf(fmaxf(floorf(__fadd_rn(__fmul_rn(fq, bw), sw)), 0.f), 50.f);
  we = (int)fminf(fmaxf(ceilf(__fadd_rn(__fmul_rn(__fadd_rn(fq, 1.f), bw), sw)), 0.f), 50.f);
}

__device__ __forceinline__ int row_of(int c, int pq) {
  return (c < NCLS) ? (c * PQN + pq) : (ROWS_CLS + (c - NCLS) * PQN + pq);
}

// ---------------- 5. fused pool + projection (P in smem, tf32 mma) ------------------
// grid (49 pq, 19 chunks of 16 rois), 128 threads. Dynamic smem: Ps[16][1028].
// Phase B: KT=64, register-double-buffered W tiles, one sync per k-iter.
#define CHUNK 16
#define PSTR 1028
__global__ __launch_bounds__(128) void k_poolproj(const float* __restrict__ rois,
                                                  const int* __restrict__ ridx) {
  extern __shared__ float Ps[];        // [CHUNK][PSTR]
  __shared__ float As2[2][32][68];
  __shared__ float biasS[32];
  __shared__ float maskS[CHUNK];
  int pq = blockIdx.x, g = blockIdx.y;
  int p = pq / 7, q = pq - p * 7;
  int t = threadIdx.x;
  int warp = t >> 5, lane = t & 31;
  int lg = lane >> 2, lt = lane & 3;

  if (t < 32) biasS[t] = (t < COMB) ? g_bias[row_of(t, pq)] : 0.f;

  // Phase A: pooled vectors into smem (identical numerics to passing R11)
  for (int rr = 0; rr < CHUNK; rr++) {
    int r = g * CHUNK + rr;
    if (r < RR) {
      int hs, he, ws, we;
      roi_geom(rois, r, p, q, hs, he, ws, we);
      int n = ridx[r];
      int cnt = (he - hs) * (we - ws);
      float rcp = (cnt > 0) ? __fdiv_rn(1.0f, (float)cnt) : 0.0f;
      const float4* sat = g_sat4 + (size_t)n * SATSP * 256;
#pragma unroll
      for (int sgm = 0; sgm < 2; sgm++) {
        int c4 = t + sgm * 128;
        float4 s11 = sat[(size_t)(he * SATN + we) * 256 + c4];
        float4 s01 = sat[(size_t)(hs * SATN + we) * 256 + c4];
        float4 s10 = sat[(size_t)(he * SATN + ws) * 256 + c4];
        float4 s00 = sat[(size_t)(hs * SATN + ws) * 256 + c4];
        float4 acc = make_float4(((s11.x - s01.x) - (s10.x - s00.x)) * rcp,
                                 ((s11.y - s01.y) - (s10.y - s00.y)) * rcp,
                                 ((s11.z - s01.z) - (s10.z - s00.z)) * rcp,
                                 ((s11.w - s01.w) - (s10.w - s00.w)) * rcp);
        *(float4*)&Ps[rr * PSTR + (c4 << 2)] = tf32r4(acc);
      }
      if (t == 0) maskS[rr] = (cnt > 0) ? 1.0f : 0.0f;
    } else {
      float4 z = make_float4(0.f, 0.f, 0.f, 0.f);
#pragma unroll
      for (int sgm = 0; sgm < 2; sgm++)
        *(float4*)&Ps[rr * PSTR + ((t + sgm * 128) << 2)] = z;
      if (t == 0) maskS[rr] = 0.f;
    }
  }

  // Phase B: S[m, roi] = W[row_of(m,pq), :] . P[roi, :]   (M=32, N=16, K=1024)
  int ms = warp >> 1, ns = warp & 1;
  float c0 = 0.f, c1 = 0.f, c2 = 0.f, c3 = 0.f;
  const float* W = (const float*)g_W4;

  int tr = t >> 4;               // 0..7
  int f4c = (t & 15) << 2;       // 0..60
  const float* wp[4];
  int wok[4];
#pragma unroll
  for (int i = 0; i < 4; i++) {
    int m = 8 * i + tr;
    wok[i] = (m < COMB);
    wp[i] = W + (size_t)row_of(wok[i] ? m : 0, pq) * CIN + f4c;
  }
  float4 wbuf[4];
#pragma unroll
  for (int i = 0; i < 4; i++)
    wbuf[i] = wok[i] ? *(const float4*)(wp[i]) : make_float4(0.f, 0.f, 0.f, 0.f);
#pragma unroll
  for (int i = 0; i < 4; i++) *(float4*)&As2[0][8 * i + tr][f4c] = wbuf[i];
  __syncthreads();   // covers Ps (phase A) + As2[0]

  for (int kt = 0; kt < 16; kt++) {
    if (kt < 15) {
      int koff = (kt + 1) << 6;
#pragma unroll
      for (int i = 0; i < 4; i++)
        wbuf[i] = wok[i] ? *(const float4*)(wp[i] + koff) : make_float4(0.f, 0.f, 0.f, 0.f);
    }
    int bufc = kt & 1;
    int kbase = kt << 6;
#pragma unroll
    for (int ks = 0; ks < 8; ks++) {
      int kc = ks << 3;
      int row = (ms << 4) + lg;
      uint32_t a0 = __float_as_uint(As2[bufc][row][kc + lt]);
      uint32_t a1 = __float_as_uint(As2[bufc][row + 8][kc + lt]);
      uint32_t a2 = __float_as_uint(As2[bufc][row][kc + 4 + lt]);
      uint32_t a3 = __float_as_uint(As2[bufc][row + 8][kc + 4 + lt]);
      int col = (ns << 3) + lg;
      uint32_t b0 = __float_as_uint(Ps[col * PSTR + kbase + kc + lt]);
      uint32_t b1 = __float_as_uint(Ps[col * PSTR + kbase + kc + 4 + lt]);
      asm volatile(
        "mma.sync.aligned.m16n8k8.row.col.f32.tf32.tf32.f32 "
        "{%0,%1,%2,%3}, {%4,%5,%6,%7}, {%8,%9}, {%0,%1,%2,%3};"
        : "+f"(c0), "+f"(c1), "+f"(c2), "+f"(c3)
        : "r"(a0), "r"(a1), "r"(a2), "r"(a3), "r"(b0), "r"(b1));
    }
    if (kt < 15) {
#pragma unroll
      for (int i = 0; i < 4; i++) *(float4*)&As2[1 - bufc][8 * i + tr][f4c] = wbuf[i];
      __syncthreads();
    }
  }

  // epilogue
  int m_lo = (ms << 4) + lg, m_hi = m_lo + 8;
  int col0 = (ns << 3) + (lt << 1);
  float b_lo = biasS[m_lo], b_hi = biasS[m_hi];
#pragma unroll
  for (int rr2 = 0; rr2 < 2; rr2++) {
    int col = col0 + rr2;
    int r = g * CHUNK + col;
    if (r < RR) {
      float mk = maskS[col];
      if (m_lo < COMB)
        g_scr[((size_t)r * COMB + m_lo) * PQN + pq] = ((rr2 ? c1 : c0) + b_lo) * mk;
      if (m_hi < COMB)
        g_scr[((size_t)r * COMB + m_hi) * PQN + pq] = ((rr2 ? c3 : c2) + b_hi) * mk;
    }
  }
}

// ---------------- 6. reduce: mean over 49 bins = sum * fl(1/49) ----------------
__global__ void k_reduce(float* __restrict__ out) {
  int idx = blockIdx.x * blockDim.x + threadIdx.x;
  if (idx >= RR * COMB) return;
  int r = idx / COMB, c = idx - r * COMB;
  const float* src = g_scr + (size_t)idx * PQN;
  float s = 0.f;
#pragma unroll
  for (int pq = 0; pq < PQN; pq++) s += src[pq];
  float mean = __fmul_rn(s, 1.0f / 49.0f);
  if (c < NCLS) out[r * NCLS + c] = mean;                  // roi_score [300,21]
  else out[RR * NCLS + r * 4 + (c - NCLS)] = mean;         // roi_locs  [300,4]
}

// ---------------- launch ----------------
extern "C" void kernel_launch(void* const* d_in, const int* in_sizes, int n_in,
                              void* d_out, int out_size) {
  const float* h    = (const float*)d_in[0];
  const float* rois = (const float*)d_in[1];
  const int*   ridx = (const int*)d_in[2];
  const float* w1   = (const float*)d_in[3];
  const float* b1   = (const float*)d_in[4];
  const float* wc   = (const float*)d_in[5];
  const float* bc   = (const float*)d_in[6];
  const float* wl   = (const float*)d_in[7];
  const float* bl   = (const float*)d_in[8];
  float* out = (float*)d_out;

  const int PSMEM = CHUNK * PSTR * 4;   // 65792 B dynamic
  cudaFuncSetAttribute(k_poolproj, cudaFuncAttributeMaxDynamicSharedMemorySize, PSMEM);

  k_prep<<<ROWS_TOT + CIN, 256>>>(wc, wl, w1);
  k_transpose<<<dim3((SPAT + 31) / 32, CIN / 32, NB), dim3(32, 8)>>>(h);
  k_fold_mma<<<dim3(CIN / 64, (ROWS_TOT + 63) / 64), 128>>>(0);
  k_sat1<<<dim3(SATN, NB, 2), 128>>>();
  k_sat2<<<dim3(SATN, NB, 2), 128>>>();
  k_bias<<<(ROWS_TOT * 32 + 255) / 256, 256>>>(wc, wl, bc, bl, b1);
  k_poolproj<<<dim3(PQN, (RR + CHUNK - 1) / CHUNK), 128, PSMEM>>>(rois, ridx);
  k_reduce<<<(RR * COMB + 255) / 256, 256>>>(out);
}